// round 6
// baseline (speedup 1.0000x reference)
#include <cuda_runtime.h>
#include <cstdint>
#include <cstddef>

#define BB 32
#define NN 2048
#define DD 128
#define HH 128

// Scratch for q/k/v activations (allocation-free rule: static device arrays).
__device__ float g_q[BB * NN * HH];
__device__ float g_k[BB * NN * HH];
__device__ float g_v[BB * NN * HH];

// ---------- packed f32x2 helpers (projection kernel) ----------
__device__ __forceinline__ unsigned long long pk2(float lo, float hi) {
    unsigned long long r;
    asm("mov.b64 %0, {%1, %2};" : "=l"(r) : "f"(lo), "f"(hi));
    return r;
}
__device__ __forceinline__ float2 upk2(unsigned long long p) {
    float2 f;
    asm("mov.b64 {%0, %1}, %2;" : "=f"(f.x), "=f"(f.y) : "l"(p));
    return f;
}
__device__ __forceinline__ unsigned long long f2fma(unsigned long long a,
                                                    unsigned long long b,
                                                    unsigned long long c) {
    unsigned long long d;
    asm("fma.rn.f32x2 %0, %1, %2, %3;" : "=l"(d) : "l"(a), "l"(b), "l"(c));
    return d;
}

__device__ __forceinline__ uint32_t tf32r(float x) {
    uint32_t r;
    asm("cvt.rna.tf32.f32 %0, %1;" : "=r"(r) : "f"(x));
    return r;
}

// warp mma: D(16x8) += A(16x8,row,tf32) * B(8x8,col,tf32), fp32 accum
__device__ __forceinline__ void mma16n8k8(float* c, const uint32_t* a,
                                          uint32_t b0, uint32_t b1) {
    asm volatile(
        "mma.sync.aligned.m16n8k8.row.col.f32.tf32.tf32.f32 "
        "{%0,%1,%2,%3}, {%4,%5,%6,%7}, {%8,%9}, {%0,%1,%2,%3};"
        : "+f"(c[0]), "+f"(c[1]), "+f"(c[2]), "+f"(c[3])
        : "r"(a[0]), "r"(a[1]), "r"(a[2]), "r"(a[3]), "r"(b0), "r"(b1));
}

__device__ __forceinline__ uint32_t smem_u32(const void* p) {
    uint32_t a;
    asm("{ .reg .u64 t; cvta.to.shared.u64 t, %1; cvt.u32.u64 %0, t; }"
        : "=r"(a) : "l"(p));
    return a;
}

#define CP_ASYNC16(dst, src)                                                \
    asm volatile("cp.async.cg.shared.global [%0], [%1], 16;" ::             \
                     "r"(dst), "l"(src) : "memory")
#define CP_COMMIT() asm volatile("cp.async.commit_group;" ::: "memory")
#define CP_WAIT0() asm volatile("cp.async.wait_group 0;" ::: "memory")
#define CP_WAIT1() asm volatile("cp.async.wait_group 1;" ::: "memory")

// ============================================================
// Kernel A: fused QKV projection, out = tanh(x @ W + b)  (FFMA2)
// Stores tf32-PRE-ROUNDED values. For q and k, the feature (h) dim is
// permuted within 8-groups: cc -> (cc&3)*2 + (cc>>2)  (QK^T invariant;
// lets the attention kernel fetch mma fragments with 8-byte loads).
// Permuted values are repacked into float4 stores via a shfl pair swap.
// ============================================================
__global__ __launch_bounds__(256, 1) void proj_kernel(
    const float* __restrict__ x,
    const float* __restrict__ Wq, const float* __restrict__ bq,
    const float* __restrict__ Wk, const float* __restrict__ bk,
    const float* __restrict__ Wv, const float* __restrict__ bv) {
    extern __shared__ float sm[];
    float* xs = sm;              // 64*128
    float* ws = sm + 64 * 128;   // 32*128

    const float* W;
    const float* bias;
    float* outp;
    bool permute;
    if (blockIdx.y == 0)      { W = Wq; bias = bq; outp = g_q; permute = true; }
    else if (blockIdx.y == 1) { W = Wk; bias = bk; outp = g_k; permute = true; }
    else                      { W = Wv; bias = bv; outp = g_v; permute = false; }

    const int tid = threadIdx.x;
    const int rowg = tid >> 4;
    const int colg = tid & 15;
    const int row0 = blockIdx.x * 64;

    {
        const float4* src = reinterpret_cast<const float4*>(x + (size_t)row0 * DD);
        float4* dst = reinterpret_cast<float4*>(xs);
#pragma unroll
        for (int t = 0; t < 8; t++) dst[tid + t * 256] = src[tid + t * 256];
    }

    unsigned long long acc[4][4];
#pragma unroll
    for (int r = 0; r < 4; r++)
#pragma unroll
        for (int c = 0; c < 4; c++) acc[r][c] = 0ull;

#pragma unroll 1
    for (int chunk = 0; chunk < 4; chunk++) {
        const int kk0 = chunk * 32;
        __syncthreads();
        {
            const float4* src = reinterpret_cast<const float4*>(W + (size_t)kk0 * HH);
            float4* dst = reinterpret_cast<float4*>(ws);
#pragma unroll
            for (int t = 0; t < 4; t++) dst[tid + t * 256] = src[tid + t * 256];
        }
        __syncthreads();

#pragma unroll 2
        for (int kkl = 0; kkl < 32; kkl++) {
            const int kk = kk0 + kkl;
            float xv[4];
#pragma unroll
            for (int r = 0; r < 4; r++) xv[r] = xs[(rowg * 4 + r) * DD + kk];
            float4 wa = *reinterpret_cast<const float4*>(ws + kkl * HH + colg * 4);
            float4 wb = *reinterpret_cast<const float4*>(ws + kkl * HH + 64 + colg * 4);
            unsigned long long wp[4];
            wp[0] = *reinterpret_cast<unsigned long long*>(&wa.x);
            wp[1] = *reinterpret_cast<unsigned long long*>(&wa.z);
            wp[2] = *reinterpret_cast<unsigned long long*>(&wb.x);
            wp[3] = *reinterpret_cast<unsigned long long*>(&wb.z);
#pragma unroll
            for (int r = 0; r < 4; r++) {
                unsigned long long xp = pk2(xv[r], xv[r]);
#pragma unroll
                for (int c = 0; c < 4; c++) acc[r][c] = f2fma(xp, wp[c], acc[r][c]);
            }
        }
    }

    float4 ba = *reinterpret_cast<const float4*>(bias + colg * 4);
    float4 bb = *reinterpret_cast<const float4*>(bias + 64 + colg * 4);
    const bool oddc = (colg & 1);
    const int gbase = (colg >> 1) * 8 + (oddc ? 4 : 0);
#pragma unroll
    for (int r = 0; r < 4; r++) {
        float2 a0 = upk2(acc[r][0]);
        float2 a1 = upk2(acc[r][1]);
        float2 a2 = upk2(acc[r][2]);
        float2 a3 = upk2(acc[r][3]);
        float v[8];
        v[0] = __uint_as_float(tf32r(tanhf(a0.x + ba.x)));
        v[1] = __uint_as_float(tf32r(tanhf(a0.y + ba.y)));
        v[2] = __uint_as_float(tf32r(tanhf(a1.x + ba.z)));
        v[3] = __uint_as_float(tf32r(tanhf(a1.y + ba.w)));
        v[4] = __uint_as_float(tf32r(tanhf(a2.x + bb.x)));
        v[5] = __uint_as_float(tf32r(tanhf(a2.y + bb.y)));
        v[6] = __uint_as_float(tf32r(tanhf(a3.x + bb.z)));
        v[7] = __uint_as_float(tf32r(tanhf(a3.y + bb.w)));
        float* orow = outp + (size_t)(row0 + rowg * 4 + r) * HH;
        if (permute) {
            // partner values (colg ^ 1)
            float p[8];
#pragma unroll
            for (int i = 0; i < 8; i++)
                p[i] = __shfl_xor_sync(0xffffffffu, v[i], 1);
            float4 lo, hi;
            if (!oddc) {
                lo.x = v[0]; lo.y = p[0]; lo.z = v[1]; lo.w = p[1];
                hi.x = v[4]; hi.y = p[4]; hi.z = v[5]; hi.w = p[5];
            } else {
                lo.x = p[2]; lo.y = v[2]; lo.z = p[3]; lo.w = v[3];
                hi.x = p[6]; hi.y = v[6]; hi.z = p[7]; hi.w = v[7];
            }
            *reinterpret_cast<float4*>(orow + gbase) = lo;
            *reinterpret_cast<float4*>(orow + 64 + gbase) = hi;
        } else {
            float4 oa, ob;
            oa.x = v[0]; oa.y = v[1]; oa.z = v[2]; oa.w = v[3];
            ob.x = v[4]; ob.y = v[5]; ob.z = v[6]; ob.w = v[7];
            *reinterpret_cast<float4*>(orow + colg * 4) = oa;
            *reinterpret_cast<float4*>(orow + 64 + colg * 4) = ob;
        }
    }
}

// ============================================================
// Kernel B: tf32 mma.sync flash attention v4.
//  - Q fragments persistent in registers (loaded once, LDG.64 via h-permute)
//  - FULL unroll of QK / convert / PV so qa/sf/pa stay register-resident
//  - K fragments fetched as 8B LDS (h-permute)
//  - split cp.async groups: wait K only at tile top, V overlaps QK+softmax
// smem: Ks[128][132] | Vs[128][136]  (u32 words)
// ============================================================
#define QLDW 132
#define VLDW 136
#define VS_OFF (128 * QLDW)
#define SMEM_ATT ((128 * QLDW + 128 * VLDW) * 4)

__global__ __launch_bounds__(256, 1) void attn_mma(
    const float* __restrict__ mask, float* __restrict__ out) {
    extern __shared__ uint32_t smw[];
    uint32_t* Ks = smw;
    uint32_t* Vs = smw + VS_OFF;
    const uint32_t smb = smem_u32(smw);

    const int tid = threadIdx.x;
    const int lane = tid & 31;
    const int w = tid >> 5;
    const int b = blockIdx.x >> 4;
    const int i0 = (blockIdx.x & 15) << 7;
    const int qp = lane >> 2;
    const int ql = lane & 3;
    const int r0 = w * 16 + qp;

    const float* kg = g_k + (size_t)(b * NN) * HH;
    const float* vg = g_v + (size_t)(b * NN) * HH;

    // ---- prologue: K0 group, then V0 group ----
#pragma unroll
    for (int t = 0; t < 16; t++) {
        const int idx = tid + t * 256;
        const int row = idx >> 5, c4 = idx & 31;
        CP_ASYNC16(smb + (uint32_t)(row * QLDW + c4 * 4) * 4, kg + idx * 4);
    }
    CP_COMMIT();
#pragma unroll
    for (int t = 0; t < 16; t++) {
        const int idx = tid + t * 256;
        const int row = idx >> 5, c4 = idx & 31;
        CP_ASYNC16(smb + (uint32_t)(VS_OFF + row * VLDW + c4 * 4) * 4, vg + idx * 4);
    }
    CP_COMMIT();

    // ---- persistent Q fragments from gmem (h-permuted rows) ----
    uint32_t qa[16][4];
    {
        const float* qr0 = g_q + ((size_t)(b * NN) + i0 + r0) * HH + 2 * ql;
        const float* qr1 = qr0 + 8 * HH;
#pragma unroll
        for (int k = 0; k < 16; k++) {
            float2 a = __ldg(reinterpret_cast<const float2*>(qr0 + k * 8));
            float2 c = __ldg(reinterpret_cast<const float2*>(qr1 + k * 8));
            qa[k][0] = __float_as_uint(a.x);
            qa[k][1] = __float_as_uint(c.x);
            qa[k][2] = __float_as_uint(a.y);
            qa[k][3] = __float_as_uint(c.y);
        }
    }

    float oa[16][4];
#pragma unroll
    for (int h = 0; h < 16; h++)
#pragma unroll
        for (int c = 0; c < 4; c++) oa[h][c] = 0.0f;
    float ls0 = 0.0f, ls1 = 0.0f;

    const float* mrow0 = mask + ((size_t)(b * NN) + i0 + r0) * NN + 2 * ql;
    const float* mrow1 = mrow0 + (size_t)8 * NN;

    const int L0 = qp * 4 + (ql >> 1);
    const bool odd = (ql & 1);

#pragma unroll 1
    for (int jt = 0; jt < 16; jt++) {
        const int j0 = jt << 7;
        CP_WAIT1();        // K[jt] landed (V[jt] may still be in flight)
        __syncthreads();

        // ---- S = Q K^T : k outer, 16 independent nb chains ----
        float sf[16][4];
#pragma unroll
        for (int nb = 0; nb < 16; nb++)
#pragma unroll
            for (int c = 0; c < 4; c++) sf[nb][c] = 0.0f;

#pragma unroll
        for (int k = 0; k < 16; k++) {
#pragma unroll
            for (int nb = 0; nb < 16; nb++) {
                uint2 kb = *reinterpret_cast<const uint2*>(
                    Ks + (nb * 8 + qp) * QLDW + k * 8 + 2 * ql);
                mma16n8k8(sf[nb], qa[k], kb.x, kb.y);
            }
        }

        // ---- mask + exp + D->A fragment conversion (registers only) ----
        uint32_t pa[16][4];
#pragma unroll
        for (int nb = 0; nb < 16; nb++) {
            const int jcol = j0 + nb * 8;
            float2 m0 = __ldg(reinterpret_cast<const float2*>(mrow0 + jcol));
            float2 m1 = __ldg(reinterpret_cast<const float2*>(mrow1 + jcol));
            uint32_t u0 = (m0.x != 0.0f) ? tf32r(__expf(sf[nb][0] - 40.0f)) : 0u;
            uint32_t u1 = (m0.y != 0.0f) ? tf32r(__expf(sf[nb][1] - 40.0f)) : 0u;
            uint32_t u2 = (m1.x != 0.0f) ? tf32r(__expf(sf[nb][2] - 40.0f)) : 0u;
            uint32_t u3 = (m1.y != 0.0f) ? tf32r(__expf(sf[nb][3] - 40.0f)) : 0u;
            ls0 += __uint_as_float(u0) + __uint_as_float(u1);
            ls1 += __uint_as_float(u2) + __uint_as_float(u3);
            uint32_t t00 = __shfl_sync(0xffffffffu, u0, L0);
            uint32_t t01 = __shfl_sync(0xffffffffu, u1, L0);
            uint32_t t10 = __shfl_sync(0xffffffffu, u2, L0);
            uint32_t t11 = __shfl_sync(0xffffffffu, u3, L0);
            uint32_t t20 = __shfl_sync(0xffffffffu, u0, L0 + 2);
            uint32_t t21 = __shfl_sync(0xffffffffu, u1, L0 + 2);
            uint32_t t30 = __shfl_sync(0xffffffffu, u2, L0 + 2);
            uint32_t t31 = __shfl_sync(0xffffffffu, u3, L0 + 2);
            pa[nb][0] = odd ? t01 : t00;
            pa[nb][1] = odd ? t11 : t10;
            pa[nb][2] = odd ? t21 : t20;
            pa[nb][3] = odd ? t31 : t30;
        }

        CP_WAIT0();        // V[jt] landed (everywhere, after the barrier)
        __syncthreads();   // also: all warps done reading Ks
        if (jt < 15) {
            const float* kn = kg + ((size_t)(j0 + 128)) * HH;
#pragma unroll
            for (int t = 0; t < 16; t++) {
                const int idx = tid + t * 256;
                const int row = idx >> 5, c4 = idx & 31;
                CP_ASYNC16(smb + (uint32_t)(row * QLDW + c4 * 4) * 4, kn + idx * 4);
            }
            CP_COMMIT();
        }

        // ---- O += P V : fully unrolled, pa register-resident ----
#pragma unroll
        for (int k = 0; k < 16; k++) {
            const uint32_t* vb = Vs + (k * 8 + ql) * VLDW + qp;
#pragma unroll
            for (int h = 0; h < 16; h++) {
                mma16n8k8(oa[h], pa[k], vb[h * 8], vb[h * 8 + 4 * VLDW]);
            }
        }
        __syncthreads();   // all warps done reading Vs
        if (jt < 15) {
            const float* vn = vg + ((size_t)(j0 + 128)) * HH;
#pragma unroll
            for (int t = 0; t < 16; t++) {
                const int idx = tid + t * 256;
                const int row = idx >> 5, c4 = idx & 31;
                CP_ASYNC16(smb + (uint32_t)(VS_OFF + row * VLDW + c4 * 4) * 4,
                           vn + idx * 4);
            }
            CP_COMMIT();
        }
    }

    // ---- epilogue: deferred quad reduction, normalize, store ----
    ls0 += __shfl_xor_sync(0xffffffffu, ls0, 1);
    ls0 += __shfl_xor_sync(0xffffffffu, ls0, 2);
    ls1 += __shfl_xor_sync(0xffffffffu, ls1, 1);
    ls1 += __shfl_xor_sync(0xffffffffu, ls1, 2);
    const float inv0 = 1.0f / ls0;
    const float inv1 = 1.0f / ls1;
    float* orow0 = out + ((size_t)(b * NN) + i0 + r0) * HH + 2 * ql;
    float* orow1 = orow0 + (size_t)8 * HH;
#pragma unroll
    for (int h = 0; h < 16; h++) {
        float2 v0, v1;
        v0.x = oa[h][0] * inv0; v0.y = oa[h][1] * inv0;
        v1.x = oa[h][2] * inv1; v1.y = oa[h][3] * inv1;
        *reinterpret_cast<float2*>(orow0 + h * 8) = v0;
        *reinterpret_cast<float2*>(orow1 + h * 8) = v1;
    }
}

extern "C" void kernel_launch(void* const* d_in, const int* in_sizes, int n_in,
                              void* d_out, int out_size) {
    const float* x    = (const float*)d_in[0];
    const float* mask = (const float*)d_in[1];
    const float* Wv   = (const float*)d_in[2];
    const float* bv   = (const float*)d_in[3];
    const float* Wk   = (const float*)d_in[4];
    const float* bk   = (const float*)d_in[5];
    const float* Wq   = (const float*)d_in[6];
    const float* bq   = (const float*)d_in[7];
    float* out = (float*)d_out;

    cudaFuncSetAttribute(proj_kernel, cudaFuncAttributeMaxDynamicSharedMemorySize,
                         49152);
    cudaFuncSetAttribute(attn_mma, cudaFuncAttributeMaxDynamicSharedMemorySize,
                         SMEM_ATT);

    proj_kernel<<<dim3(1024, 3, 1), 256, 49152>>>(x, Wq, bq, Wk, bk, Wv, bv);
    attn_mma<<<512, 256, SMEM_ATT>>>(mask, out);
}

// round 7
// speedup vs baseline: 1.2684x; 1.2684x over previous
#include <cuda_runtime.h>
#include <cstdint>
#include <cstddef>

#define BB 32
#define NN 2048
#define DD 128
#define HH 128

// Scratch for q/k/v activations (allocation-free rule: static device arrays).
__device__ float g_q[BB * NN * HH];
__device__ float g_k[BB * NN * HH];
__device__ float g_v[BB * NN * HH];

// ---------- packed f32x2 helpers (projection kernel) ----------
__device__ __forceinline__ unsigned long long pk2(float lo, float hi) {
    unsigned long long r;
    asm("mov.b64 %0, {%1, %2};" : "=l"(r) : "f"(lo), "f"(hi));
    return r;
}
__device__ __forceinline__ float2 upk2(unsigned long long p) {
    float2 f;
    asm("mov.b64 {%0, %1}, %2;" : "=f"(f.x), "=f"(f.y) : "l"(p));
    return f;
}
__device__ __forceinline__ unsigned long long f2fma(unsigned long long a,
                                                    unsigned long long b,
                                                    unsigned long long c) {
    unsigned long long d;
    asm("fma.rn.f32x2 %0, %1, %2, %3;" : "=l"(d) : "l"(a), "l"(b), "l"(c));
    return d;
}

__device__ __forceinline__ uint32_t tf32r(float x) {
    uint32_t r;
    asm("cvt.rna.tf32.f32 %0, %1;" : "=r"(r) : "f"(x));
    return r;
}

// warp mma: D(16x8) += A(16x8,row,tf32) * B(8x8,col,tf32), fp32 accum
__device__ __forceinline__ void mma16n8k8(float* c, const uint32_t* a,
                                          uint32_t b0, uint32_t b1) {
    asm volatile(
        "mma.sync.aligned.m16n8k8.row.col.f32.tf32.tf32.f32 "
        "{%0,%1,%2,%3}, {%4,%5,%6,%7}, {%8,%9}, {%0,%1,%2,%3};"
        : "+f"(c[0]), "+f"(c[1]), "+f"(c[2]), "+f"(c[3])
        : "r"(a[0]), "r"(a[1]), "r"(a[2]), "r"(a[3]), "r"(b0), "r"(b1));
}

__device__ __forceinline__ uint32_t smem_u32(const void* p) {
    uint32_t a;
    asm("{ .reg .u64 t; cvta.to.shared.u64 t, %1; cvt.u32.u64 %0, t; }"
        : "=r"(a) : "l"(p));
    return a;
}

#define CP_ASYNC16(dst, src)                                                \
    asm volatile("cp.async.cg.shared.global [%0], [%1], 16;" ::             \
                     "r"(dst), "l"(src) : "memory")
#define CP_COMMIT() asm volatile("cp.async.commit_group;" ::: "memory")
#define CP_WAIT0() asm volatile("cp.async.wait_group 0;" ::: "memory")

// ============================================================
// Kernel A: fused QKV projection, out = tanh(x @ W + b)  (FFMA2)
// Stores tf32-PRE-ROUNDED values. For q and k, the feature (h) dim is
// permuted within 8-groups: cc -> (cc&3)*2 + (cc>>2)  (QK^T invariant;
// lets the attention kernel fetch mma fragments with 8-byte loads).
// Permuted values are repacked into float4 stores via a shfl pair swap.
// ============================================================
__global__ __launch_bounds__(256, 1) void proj_kernel(
    const float* __restrict__ x,
    const float* __restrict__ Wq, const float* __restrict__ bq,
    const float* __restrict__ Wk, const float* __restrict__ bk,
    const float* __restrict__ Wv, const float* __restrict__ bv) {
    extern __shared__ float sm[];
    float* xs = sm;              // 64*128
    float* ws = sm + 64 * 128;   // 32*128

    const float* W;
    const float* bias;
    float* outp;
    bool permute;
    if (blockIdx.y == 0)      { W = Wq; bias = bq; outp = g_q; permute = true; }
    else if (blockIdx.y == 1) { W = Wk; bias = bk; outp = g_k; permute = true; }
    else                      { W = Wv; bias = bv; outp = g_v; permute = false; }

    const int tid = threadIdx.x;
    const int rowg = tid >> 4;
    const int colg = tid & 15;
    const int row0 = blockIdx.x * 64;

    {
        const float4* src = reinterpret_cast<const float4*>(x + (size_t)row0 * DD);
        float4* dst = reinterpret_cast<float4*>(xs);
#pragma unroll
        for (int t = 0; t < 8; t++) dst[tid + t * 256] = src[tid + t * 256];
    }

    unsigned long long acc[4][4];
#pragma unroll
    for (int r = 0; r < 4; r++)
#pragma unroll
        for (int c = 0; c < 4; c++) acc[r][c] = 0ull;

#pragma unroll 1
    for (int chunk = 0; chunk < 4; chunk++) {
        const int kk0 = chunk * 32;
        __syncthreads();
        {
            const float4* src = reinterpret_cast<const float4*>(W + (size_t)kk0 * HH);
            float4* dst = reinterpret_cast<float4*>(ws);
#pragma unroll
            for (int t = 0; t < 4; t++) dst[tid + t * 256] = src[tid + t * 256];
        }
        __syncthreads();

#pragma unroll 2
        for (int kkl = 0; kkl < 32; kkl++) {
            const int kk = kk0 + kkl;
            float xv[4];
#pragma unroll
            for (int r = 0; r < 4; r++) xv[r] = xs[(rowg * 4 + r) * DD + kk];
            float4 wa = *reinterpret_cast<const float4*>(ws + kkl * HH + colg * 4);
            float4 wb = *reinterpret_cast<const float4*>(ws + kkl * HH + 64 + colg * 4);
            unsigned long long wp[4];
            wp[0] = *reinterpret_cast<unsigned long long*>(&wa.x);
            wp[1] = *reinterpret_cast<unsigned long long*>(&wa.z);
            wp[2] = *reinterpret_cast<unsigned long long*>(&wb.x);
            wp[3] = *reinterpret_cast<unsigned long long*>(&wb.z);
#pragma unroll
            for (int r = 0; r < 4; r++) {
                unsigned long long xp = pk2(xv[r], xv[r]);
#pragma unroll
                for (int c = 0; c < 4; c++) acc[r][c] = f2fma(xp, wp[c], acc[r][c]);
            }
        }
    }

    float4 ba = *reinterpret_cast<const float4*>(bias + colg * 4);
    float4 bb = *reinterpret_cast<const float4*>(bias + 64 + colg * 4);
    const bool oddc = (colg & 1);
    const int gbase = (colg >> 1) * 8 + (oddc ? 4 : 0);
#pragma unroll
    for (int r = 0; r < 4; r++) {
        float2 a0 = upk2(acc[r][0]);
        float2 a1 = upk2(acc[r][1]);
        float2 a2 = upk2(acc[r][2]);
        float2 a3 = upk2(acc[r][3]);
        float v[8];
        v[0] = __uint_as_float(tf32r(tanhf(a0.x + ba.x)));
        v[1] = __uint_as_float(tf32r(tanhf(a0.y + ba.y)));
        v[2] = __uint_as_float(tf32r(tanhf(a1.x + ba.z)));
        v[3] = __uint_as_float(tf32r(tanhf(a1.y + ba.w)));
        v[4] = __uint_as_float(tf32r(tanhf(a2.x + bb.x)));
        v[5] = __uint_as_float(tf32r(tanhf(a2.y + bb.y)));
        v[6] = __uint_as_float(tf32r(tanhf(a3.x + bb.z)));
        v[7] = __uint_as_float(tf32r(tanhf(a3.y + bb.w)));
        float* orow = outp + (size_t)(row0 + rowg * 4 + r) * HH;
        if (permute) {
            float p[8];
#pragma unroll
            for (int i = 0; i < 8; i++)
                p[i] = __shfl_xor_sync(0xffffffffu, v[i], 1);
            float4 lo, hi;
            if (!oddc) {
                lo.x = v[0]; lo.y = p[0]; lo.z = v[1]; lo.w = p[1];
                hi.x = v[4]; hi.y = p[4]; hi.z = v[5]; hi.w = p[5];
            } else {
                lo.x = p[2]; lo.y = v[2]; lo.z = p[3]; lo.w = v[3];
                hi.x = p[6]; hi.y = v[6]; hi.z = p[7]; hi.w = v[7];
            }
            *reinterpret_cast<float4*>(orow + gbase) = lo;
            *reinterpret_cast<float4*>(orow + 64 + gbase) = hi;
        } else {
            float4 oa, ob;
            oa.x = v[0]; oa.y = v[1]; oa.z = v[2]; oa.w = v[3];
            ob.x = v[4]; ob.y = v[5]; ob.z = v[6]; ob.w = v[7];
            *reinterpret_cast<float4*>(orow + colg * 4) = oa;
            *reinterpret_cast<float4*>(orow + 64 + colg * 4) = ob;
        }
    }
}

// ============================================================
// Kernel B: tf32 mma.sync flash attention v5.
//  - j-tile processed in TWO 64-wide halves; each half does
//    QK(8 nb) -> convert -> PV immediately, so sf/pa live sets
//    never exceed 32 regs each (no spills; peak ~220 regs).
//  - Q fragments persistent in registers (LDG.64 via h-permute)
//  - mask loads prefetched at top of each half (latency hidden by QK)
//  - single cp.async commit group per tile, waited at tile top
// smem: Ks[128][132] | Vs[128][136]  (u32 words)
// ============================================================
#define QLDW 132
#define VLDW 136
#define VS_OFF (128 * QLDW)
#define SMEM_ATT ((128 * QLDW + 128 * VLDW) * 4)

__global__ __launch_bounds__(256, 1) void attn_mma(
    const float* __restrict__ mask, float* __restrict__ out) {
    extern __shared__ uint32_t smw[];
    uint32_t* Ks = smw;
    uint32_t* Vs = smw + VS_OFF;
    const uint32_t smb = smem_u32(smw);

    const int tid = threadIdx.x;
    const int lane = tid & 31;
    const int w = tid >> 5;
    const int b = blockIdx.x >> 4;
    const int i0 = (blockIdx.x & 15) << 7;
    const int qp = lane >> 2;
    const int ql = lane & 3;
    const int r0 = w * 16 + qp;

    const float* kg = g_k + (size_t)(b * NN) * HH;
    const float* vg = g_v + (size_t)(b * NN) * HH;

    // ---- prologue: K0 + V0 in one commit group ----
#pragma unroll
    for (int t = 0; t < 16; t++) {
        const int idx = tid + t * 256;
        const int row = idx >> 5, c4 = idx & 31;
        CP_ASYNC16(smb + (uint32_t)(row * QLDW + c4 * 4) * 4, kg + idx * 4);
        CP_ASYNC16(smb + (uint32_t)(VS_OFF + row * VLDW + c4 * 4) * 4, vg + idx * 4);
    }
    CP_COMMIT();

    // ---- persistent Q fragments from gmem (h-permuted rows) ----
    uint32_t qa[16][4];
    {
        const float* qr0 = g_q + ((size_t)(b * NN) + i0 + r0) * HH + 2 * ql;
        const float* qr1 = qr0 + 8 * HH;
#pragma unroll
        for (int k = 0; k < 16; k++) {
            float2 a = __ldg(reinterpret_cast<const float2*>(qr0 + k * 8));
            float2 c = __ldg(reinterpret_cast<const float2*>(qr1 + k * 8));
            qa[k][0] = __float_as_uint(a.x);
            qa[k][1] = __float_as_uint(c.x);
            qa[k][2] = __float_as_uint(a.y);
            qa[k][3] = __float_as_uint(c.y);
        }
    }

    float oa[16][4];
#pragma unroll
    for (int h = 0; h < 16; h++)
#pragma unroll
        for (int c = 0; c < 4; c++) oa[h][c] = 0.0f;
    float ls0 = 0.0f, ls1 = 0.0f;

    const float* mrow0 = mask + ((size_t)(b * NN) + i0 + r0) * NN + 2 * ql;
    const float* mrow1 = mrow0 + (size_t)8 * NN;

    const int L0 = qp * 4 + (ql >> 1);
    const bool odd = (ql & 1);

#pragma unroll 1
    for (int jt = 0; jt < 16; jt++) {
        const int j0 = jt << 7;
        CP_WAIT0();
        __syncthreads();   // K[jt], V[jt] visible everywhere

#pragma unroll 1
        for (int half = 0; half < 2; half++) {
            const int nb0 = half * 8;

            // ---- prefetch this half's mask (hidden behind QK) ----
            float2 mh0[8], mh1[8];
#pragma unroll
            for (int nb = 0; nb < 8; nb++) {
                const int jcol = j0 + (nb0 + nb) * 8;
                mh0[nb] = __ldg(reinterpret_cast<const float2*>(mrow0 + jcol));
                mh1[nb] = __ldg(reinterpret_cast<const float2*>(mrow1 + jcol));
            }

            // ---- S half = Q K^T : 8 independent nb chains ----
            float sf[8][4];
#pragma unroll
            for (int nb = 0; nb < 8; nb++)
#pragma unroll
                for (int c = 0; c < 4; c++) sf[nb][c] = 0.0f;

#pragma unroll
            for (int k = 0; k < 16; k++) {
#pragma unroll
                for (int nb = 0; nb < 8; nb++) {
                    uint2 kb = *reinterpret_cast<const uint2*>(
                        Ks + ((nb0 + nb) * 8 + qp) * QLDW + k * 8 + 2 * ql);
                    mma16n8k8(sf[nb], qa[k], kb.x, kb.y);
                }
            }

            // ---- mask + exp + D->A conversion (sf dies, pa born) ----
            uint32_t pa[8][4];
#pragma unroll
            for (int nb = 0; nb < 8; nb++) {
                uint32_t u0 = (mh0[nb].x != 0.0f) ? tf32r(__expf(sf[nb][0] - 40.0f)) : 0u;
                uint32_t u1 = (mh0[nb].y != 0.0f) ? tf32r(__expf(sf[nb][1] - 40.0f)) : 0u;
                uint32_t u2 = (mh1[nb].x != 0.0f) ? tf32r(__expf(sf[nb][2] - 40.0f)) : 0u;
                uint32_t u3 = (mh1[nb].y != 0.0f) ? tf32r(__expf(sf[nb][3] - 40.0f)) : 0u;
                ls0 += __uint_as_float(u0) + __uint_as_float(u1);
                ls1 += __uint_as_float(u2) + __uint_as_float(u3);
                uint32_t t00 = __shfl_sync(0xffffffffu, u0, L0);
                uint32_t t01 = __shfl_sync(0xffffffffu, u1, L0);
                uint32_t t10 = __shfl_sync(0xffffffffu, u2, L0);
                uint32_t t11 = __shfl_sync(0xffffffffu, u3, L0);
                uint32_t t20 = __shfl_sync(0xffffffffu, u0, L0 + 2);
                uint32_t t21 = __shfl_sync(0xffffffffu, u1, L0 + 2);
                uint32_t t30 = __shfl_sync(0xffffffffu, u2, L0 + 2);
                uint32_t t31 = __shfl_sync(0xffffffffu, u3, L0 + 2);
                pa[nb][0] = odd ? t01 : t00;
                pa[nb][1] = odd ? t11 : t10;
                pa[nb][2] = odd ? t21 : t20;
                pa[nb][3] = odd ? t31 : t30;
            }

            // ---- O += P V over this half's 64 j values ----
#pragma unroll
            for (int k = 0; k < 8; k++) {
                const uint32_t* vb = Vs + ((nb0 + k) * 8 + ql) * VLDW + qp;
#pragma unroll
                for (int h = 0; h < 16; h++) {
                    mma16n8k8(oa[h], pa[k], vb[h * 8], vb[h * 8 + 4 * VLDW]);
                }
            }
        }

        __syncthreads();   // all warps done reading Ks, Vs
        if (jt < 15) {
            const float* kn = kg + ((size_t)(j0 + 128)) * HH;
            const float* vn = vg + ((size_t)(j0 + 128)) * HH;
#pragma unroll
            for (int t = 0; t < 16; t++) {
                const int idx = tid + t * 256;
                const int row = idx >> 5, c4 = idx & 31;
                CP_ASYNC16(smb + (uint32_t)(row * QLDW + c4 * 4) * 4, kn + idx * 4);
                CP_ASYNC16(smb + (uint32_t)(VS_OFF + row * VLDW + c4 * 4) * 4,
                           vn + idx * 4);
            }
            CP_COMMIT();
        }
    }

    // ---- epilogue: deferred quad reduction, normalize, store ----
    ls0 += __shfl_xor_sync(0xffffffffu, ls0, 1);
    ls0 += __shfl_xor_sync(0xffffffffu, ls0, 2);
    ls1 += __shfl_xor_sync(0xffffffffu, ls1, 1);
    ls1 += __shfl_xor_sync(0xffffffffu, ls1, 2);
    const float inv0 = 1.0f / ls0;
    const float inv1 = 1.0f / ls1;
    float* orow0 = out + ((size_t)(b * NN) + i0 + r0) * HH + 2 * ql;
    float* orow1 = orow0 + (size_t)8 * HH;
#pragma unroll
    for (int h = 0; h < 16; h++) {
        float2 v0, v1;
        v0.x = oa[h][0] * inv0; v0.y = oa[h][1] * inv0;
        v1.x = oa[h][2] * inv1; v1.y = oa[h][3] * inv1;
        *reinterpret_cast<float2*>(orow0 + h * 8) = v0;
        *reinterpret_cast<float2*>(orow1 + h * 8) = v1;
    }
}

extern "C" void kernel_launch(void* const* d_in, const int* in_sizes, int n_in,
                              void* d_out, int out_size) {
    const float* x    = (const float*)d_in[0];
    const float* mask = (const float*)d_in[1];
    const float* Wv   = (const float*)d_in[2];
    const float* bv   = (const float*)d_in[3];
    const float* Wk   = (const float*)d_in[4];
    const float* bk   = (const float*)d_in[5];
    const float* Wq   = (const float*)d_in[6];
    const float* bq   = (const float*)d_in[7];
    float* out = (float*)d_out;

    cudaFuncSetAttribute(proj_kernel, cudaFuncAttributeMaxDynamicSharedMemorySize,
                         49152);
    cudaFuncSetAttribute(attn_mma, cudaFuncAttributeMaxDynamicSharedMemorySize,
                         SMEM_ATT);

    proj_kernel<<<dim3(1024, 3, 1), 256, 49152>>>(x, Wq, bq, Wk, bk, Wv, bv);
    attn_mma<<<512, 256, SMEM_ATT>>>(mask, out);
}

// round 8
// speedup vs baseline: 1.2818x; 1.0106x over previous
#include <cuda_runtime.h>
#include <cstdint>
#include <cstddef>

#define BB 32
#define NN 2048
#define DD 128
#define HH 128

// Scratch for q/k/v activations (allocation-free rule: static device arrays).
__device__ float g_q[BB * NN * HH];
__device__ float g_k[BB * NN * HH];
__device__ float g_v[BB * NN * HH];

// ---------- packed f32x2 helpers (projection kernel) ----------
__device__ __forceinline__ unsigned long long pk2(float lo, float hi) {
    unsigned long long r;
    asm("mov.b64 %0, {%1, %2};" : "=l"(r) : "f"(lo), "f"(hi));
    return r;
}
__device__ __forceinline__ float2 upk2(unsigned long long p) {
    float2 f;
    asm("mov.b64 {%0, %1}, %2;" : "=f"(f.x), "=f"(f.y) : "l"(p));
    return f;
}
__device__ __forceinline__ unsigned long long f2fma(unsigned long long a,
                                                    unsigned long long b,
                                                    unsigned long long c) {
    unsigned long long d;
    asm("fma.rn.f32x2 %0, %1, %2, %3;" : "=l"(d) : "l"(a), "l"(b), "l"(c));
    return d;
}

__device__ __forceinline__ uint32_t tf32r(float x) {
    uint32_t r;
    asm("cvt.rna.tf32.f32 %0, %1;" : "=r"(r) : "f"(x));
    return r;
}

// warp mma: D(16x8) += A(16x8,row,tf32) * B(8x8,col,tf32), fp32 accum
__device__ __forceinline__ void mma16n8k8(float* c, const uint32_t* a,
                                          uint32_t b0, uint32_t b1) {
    asm volatile(
        "mma.sync.aligned.m16n8k8.row.col.f32.tf32.tf32.f32 "
        "{%0,%1,%2,%3}, {%4,%5,%6,%7}, {%8,%9}, {%0,%1,%2,%3};"
        : "+f"(c[0]), "+f"(c[1]), "+f"(c[2]), "+f"(c[3])
        : "r"(a[0]), "r"(a[1]), "r"(a[2]), "r"(a[3]), "r"(b0), "r"(b1));
}

__device__ __forceinline__ uint32_t smem_u32(const void* p) {
    uint32_t a;
    asm("{ .reg .u64 t; cvta.to.shared.u64 t, %1; cvt.u32.u64 %0, t; }"
        : "=r"(a) : "l"(p));
    return a;
}

#define CP_ASYNC16(dst, src)                                                \
    asm volatile("cp.async.cg.shared.global [%0], [%1], 16;" ::             \
                     "r"(dst), "l"(src) : "memory")
#define CP_COMMIT() asm volatile("cp.async.commit_group;" ::: "memory")
#define CP_WAIT0() asm volatile("cp.async.wait_group 0;" ::: "memory")
#define CP_WAIT1() asm volatile("cp.async.wait_group 1;" ::: "memory")

// ============================================================
// Kernel A: fused QKV projection, out = tanh(x @ W + b)  (FFMA2)
// Stores tf32-PRE-ROUNDED values. For q and k, the feature (h) dim is
// permuted within 8-groups: cc -> (cc&3)*2 + (cc>>2)  (QK^T invariant;
// lets the attention kernel fetch mma fragments with 8-byte loads).
// ============================================================
__global__ __launch_bounds__(256, 1) void proj_kernel(
    const float* __restrict__ x,
    const float* __restrict__ Wq, const float* __restrict__ bq,
    const float* __restrict__ Wk, const float* __restrict__ bk,
    const float* __restrict__ Wv, const float* __restrict__ bv) {
    extern __shared__ float sm[];
    float* xs = sm;              // 64*128
    float* ws = sm + 64 * 128;   // 32*128

    const float* W;
    const float* bias;
    float* outp;
    bool permute;
    if (blockIdx.y == 0)      { W = Wq; bias = bq; outp = g_q; permute = true; }
    else if (blockIdx.y == 1) { W = Wk; bias = bk; outp = g_k; permute = true; }
    else                      { W = Wv; bias = bv; outp = g_v; permute = false; }

    const int tid = threadIdx.x;
    const int rowg = tid >> 4;
    const int colg = tid & 15;
    const int row0 = blockIdx.x * 64;

    {
        const float4* src = reinterpret_cast<const float4*>(x + (size_t)row0 * DD);
        float4* dst = reinterpret_cast<float4*>(xs);
#pragma unroll
        for (int t = 0; t < 8; t++) dst[tid + t * 256] = src[tid + t * 256];
    }

    unsigned long long acc[4][4];
#pragma unroll
    for (int r = 0; r < 4; r++)
#pragma unroll
        for (int c = 0; c < 4; c++) acc[r][c] = 0ull;

#pragma unroll 1
    for (int chunk = 0; chunk < 4; chunk++) {
        const int kk0 = chunk * 32;
        __syncthreads();
        {
            const float4* src = reinterpret_cast<const float4*>(W + (size_t)kk0 * HH);
            float4* dst = reinterpret_cast<float4*>(ws);
#pragma unroll
            for (int t = 0; t < 4; t++) dst[tid + t * 256] = src[tid + t * 256];
        }
        __syncthreads();

#pragma unroll 2
        for (int kkl = 0; kkl < 32; kkl++) {
            const int kk = kk0 + kkl;
            float xv[4];
#pragma unroll
            for (int r = 0; r < 4; r++) xv[r] = xs[(rowg * 4 + r) * DD + kk];
            float4 wa = *reinterpret_cast<const float4*>(ws + kkl * HH + colg * 4);
            float4 wb = *reinterpret_cast<const float4*>(ws + kkl * HH + 64 + colg * 4);
            unsigned long long wp[4];
            wp[0] = *reinterpret_cast<unsigned long long*>(&wa.x);
            wp[1] = *reinterpret_cast<unsigned long long*>(&wa.z);
            wp[2] = *reinterpret_cast<unsigned long long*>(&wb.x);
            wp[3] = *reinterpret_cast<unsigned long long*>(&wb.z);
#pragma unroll
            for (int r = 0; r < 4; r++) {
                unsigned long long xp = pk2(xv[r], xv[r]);
#pragma unroll
                for (int c = 0; c < 4; c++) acc[r][c] = f2fma(xp, wp[c], acc[r][c]);
            }
        }
    }

    float4 ba = *reinterpret_cast<const float4*>(bias + colg * 4);
    float4 bb = *reinterpret_cast<const float4*>(bias + 64 + colg * 4);
    const bool oddc = (colg & 1);
    const int gbase = (colg >> 1) * 8 + (oddc ? 4 : 0);
#pragma unroll
    for (int r = 0; r < 4; r++) {
        float2 a0 = upk2(acc[r][0]);
        float2 a1 = upk2(acc[r][1]);
        float2 a2 = upk2(acc[r][2]);
        float2 a3 = upk2(acc[r][3]);
        float v[8];
        v[0] = __uint_as_float(tf32r(tanhf(a0.x + ba.x)));
        v[1] = __uint_as_float(tf32r(tanhf(a0.y + ba.y)));
        v[2] = __uint_as_float(tf32r(tanhf(a1.x + ba.z)));
        v[3] = __uint_as_float(tf32r(tanhf(a1.y + ba.w)));
        v[4] = __uint_as_float(tf32r(tanhf(a2.x + bb.x)));
        v[5] = __uint_as_float(tf32r(tanhf(a2.y + bb.y)));
        v[6] = __uint_as_float(tf32r(tanhf(a3.x + bb.z)));
        v[7] = __uint_as_float(tf32r(tanhf(a3.y + bb.w)));
        float* orow = outp + (size_t)(row0 + rowg * 4 + r) * HH;
        if (permute) {
            float p[8];
#pragma unroll
            for (int i = 0; i < 8; i++)
                p[i] = __shfl_xor_sync(0xffffffffu, v[i], 1);
            float4 lo, hi;
            if (!oddc) {
                lo.x = v[0]; lo.y = p[0]; lo.z = v[1]; lo.w = p[1];
                hi.x = v[4]; hi.y = p[4]; hi.z = v[5]; hi.w = p[5];
            } else {
                lo.x = p[2]; lo.y = v[2]; lo.z = p[3]; lo.w = v[3];
                hi.x = p[6]; hi.y = v[6]; hi.z = p[7]; hi.w = v[7];
            }
            *reinterpret_cast<float4*>(orow + gbase) = lo;
            *reinterpret_cast<float4*>(orow + 64 + gbase) = hi;
        } else {
            float4 oa, ob;
            oa.x = v[0]; oa.y = v[1]; oa.z = v[2]; oa.w = v[3];
            ob.x = v[4]; ob.y = v[5]; ob.z = v[6]; ob.w = v[7];
            *reinterpret_cast<float4*>(orow + colg * 4) = oa;
            *reinterpret_cast<float4*>(orow + 64 + colg * 4) = ob;
        }
    }
}

// ============================================================
// Kernel B: tf32 mma.sync flash attention v6.
//  - j-tile 64, DOUBLE-BUFFERED K/V/mask stages (cp.async overlaps compute)
//  - per-nb fusion: QK (two 8-deep chains) -> convert -> PV, sf/pa transient
//    => peak regs ~185, no spills
//  - Q fragments persistent in registers; mask read from smem
// Stage layout (u32 words): K[64][132] @0 | V[64][136] @8448 | M[128][68] @17152
// ============================================================
#define STW 25856            // words per stage
#define ST_V 8448
#define ST_M 17152
#define SMEM_ATT (2 * STW * 4)   // 206848 bytes

__device__ __forceinline__ void stage_copy(uint32_t smb, int stage,
                                           const float* kg, const float* vg,
                                           const float* mbase, int jj0, int tid) {
    const uint32_t sb = smb + (uint32_t)(stage * STW) * 4;
#pragma unroll
    for (int t = 0; t < 8; t++) {
        const int idx = tid + t * 256;
        const int row = idx >> 5, c4 = idx & 31;
        CP_ASYNC16(sb + (uint32_t)(row * 132 + c4 * 4) * 4,
                   kg + (size_t)(jj0 + row) * HH + c4 * 4);
        CP_ASYNC16(sb + (uint32_t)(ST_V + row * 136 + c4 * 4) * 4,
                   vg + (size_t)(jj0 + row) * HH + c4 * 4);
    }
#pragma unroll
    for (int t = 0; t < 8; t++) {
        const int idx = tid + t * 256;
        const int row = idx >> 4, c4 = idx & 15;
        CP_ASYNC16(sb + (uint32_t)(ST_M + row * 68 + c4 * 4) * 4,
                   mbase + (size_t)row * NN + jj0 + c4 * 4);
    }
}

__global__ __launch_bounds__(256, 1) void attn_mma(
    const float* __restrict__ mask, float* __restrict__ out) {
    extern __shared__ uint32_t smw[];
    const uint32_t smb = smem_u32(smw);

    const int tid = threadIdx.x;
    const int lane = tid & 31;
    const int w = tid >> 5;
    const int b = blockIdx.x >> 4;
    const int i0 = (blockIdx.x & 15) << 7;
    const int qp = lane >> 2;
    const int ql = lane & 3;
    const int r0 = w * 16 + qp;

    const float* kg = g_k + (size_t)(b * NN) * HH;
    const float* vg = g_v + (size_t)(b * NN) * HH;
    const float* mbase = mask + ((size_t)(b * NN) + i0) * NN;

    // ---- prologue: stages 0 and 1 in flight ----
    stage_copy(smb, 0, kg, vg, mbase, 0, tid);
    CP_COMMIT();
    stage_copy(smb, 1, kg, vg, mbase, 64, tid);
    CP_COMMIT();

    // ---- persistent Q fragments from gmem (h-permuted rows) ----
    uint32_t qa[16][4];
    {
        const float* qr0 = g_q + ((size_t)(b * NN) + i0 + r0) * HH + 2 * ql;
        const float* qr1 = qr0 + 8 * HH;
#pragma unroll
        for (int k = 0; k < 16; k++) {
            float2 a = __ldg(reinterpret_cast<const float2*>(qr0 + k * 8));
            float2 c = __ldg(reinterpret_cast<const float2*>(qr1 + k * 8));
            qa[k][0] = __float_as_uint(a.x);
            qa[k][1] = __float_as_uint(c.x);
            qa[k][2] = __float_as_uint(a.y);
            qa[k][3] = __float_as_uint(c.y);
        }
    }

    float oa[16][4];
#pragma unroll
    for (int h = 0; h < 16; h++)
#pragma unroll
        for (int c = 0; c < 4; c++) oa[h][c] = 0.0f;
    float ls0 = 0.0f, ls1 = 0.0f;

    const int L0 = qp * 4 + (ql >> 1);
    const bool odd = (ql & 1);

#pragma unroll 1
    for (int jt = 0; jt < 32; jt++) {
        if (jt < 30) { CP_WAIT1(); } else { CP_WAIT0(); }
        __syncthreads();   // stage jt resident and visible

        const uint32_t* sK = smw + (jt & 1) * STW;
        const uint32_t* sV = sK + ST_V;
        const uint32_t* sM = sK + ST_M;

#pragma unroll 2
        for (int nb = 0; nb < 8; nb++) {
            // ---- QK: 16 MMAs, two 8-deep chains ----
            float sfa[4] = {0.0f, 0.0f, 0.0f, 0.0f};
            float sfb[4] = {0.0f, 0.0f, 0.0f, 0.0f};
            const uint32_t* kb = sK + (nb * 8 + qp) * 132 + 2 * ql;
#pragma unroll
            for (int k = 0; k < 8; k++) {
                uint2 k0 = *reinterpret_cast<const uint2*>(kb + (2 * k) * 8);
                mma16n8k8(sfa, qa[2 * k], k0.x, k0.y);
                uint2 k1 = *reinterpret_cast<const uint2*>(kb + (2 * k + 1) * 8);
                mma16n8k8(sfb, qa[2 * k + 1], k1.x, k1.y);
            }

            // ---- mask (smem) + exp + D->A conversion ----
            const uint32_t* mrow = sM + r0 * 68 + nb * 8 + 2 * ql;
            float2 m0 = *reinterpret_cast<const float2*>(mrow);
            float2 m1 = *reinterpret_cast<const float2*>(mrow + 8 * 68);
            float s0 = sfa[0] + sfb[0];
            float s1 = sfa[1] + sfb[1];
            float s2 = sfa[2] + sfb[2];
            float s3 = sfa[3] + sfb[3];
            uint32_t u0 = (m0.x != 0.0f) ? tf32r(__expf(s0 - 40.0f)) : 0u;
            uint32_t u1 = (m0.y != 0.0f) ? tf32r(__expf(s1 - 40.0f)) : 0u;
            uint32_t u2 = (m1.x != 0.0f) ? tf32r(__expf(s2 - 40.0f)) : 0u;
            uint32_t u3 = (m1.y != 0.0f) ? tf32r(__expf(s3 - 40.0f)) : 0u;
            ls0 += __uint_as_float(u0) + __uint_as_float(u1);
            ls1 += __uint_as_float(u2) + __uint_as_float(u3);
            uint32_t pa[4];
            {
                uint32_t t00 = __shfl_sync(0xffffffffu, u0, L0);
                uint32_t t01 = __shfl_sync(0xffffffffu, u1, L0);
                uint32_t t10 = __shfl_sync(0xffffffffu, u2, L0);
                uint32_t t11 = __shfl_sync(0xffffffffu, u3, L0);
                uint32_t t20 = __shfl_sync(0xffffffffu, u0, L0 + 2);
                uint32_t t21 = __shfl_sync(0xffffffffu, u1, L0 + 2);
                uint32_t t30 = __shfl_sync(0xffffffffu, u2, L0 + 2);
                uint32_t t31 = __shfl_sync(0xffffffffu, u3, L0 + 2);
                pa[0] = odd ? t01 : t00;
                pa[1] = odd ? t11 : t10;
                pa[2] = odd ? t21 : t20;
                pa[3] = odd ? t31 : t30;
            }

            // ---- PV: 16 independent MMAs into oa ----
            const uint32_t* vb = sV + (nb * 8 + ql) * 136 + qp;
#pragma unroll
            for (int h = 0; h < 16; h++) {
                mma16n8k8(oa[h], pa, vb[h * 8], vb[h * 8 + 4 * 136]);
            }
        }

        __syncthreads();   // all warps done with stage jt
        if (jt < 30) {
            stage_copy(smb, jt & 1, kg, vg, mbase, (jt + 2) * 64, tid);
            CP_COMMIT();
        }
    }

    // ---- epilogue: quad reduction, normalize, store ----
    ls0 += __shfl_xor_sync(0xffffffffu, ls0, 1);
    ls0 += __shfl_xor_sync(0xffffffffu, ls0, 2);
    ls1 += __shfl_xor_sync(0xffffffffu, ls1, 1);
    ls1 += __shfl_xor_sync(0xffffffffu, ls1, 2);
    const float inv0 = 1.0f / ls0;
    const float inv1 = 1.0f / ls1;
    float* orow0 = out + ((size_t)(b * NN) + i0 + r0) * HH + 2 * ql;
    float* orow1 = orow0 + (size_t)8 * HH;
#pragma unroll
    for (int h = 0; h < 16; h++) {
        float2 v0, v1;
        v0.x = oa[h][0] * inv0; v0.y = oa[h][1] * inv0;
        v1.x = oa[h][2] * inv1; v1.y = oa[h][3] * inv1;
        *reinterpret_cast<float2*>(orow0 + h * 8) = v0;
        *reinterpret_cast<float2*>(orow1 + h * 8) = v1;
    }
}

extern "C" void kernel_launch(void* const* d_in, const int* in_sizes, int n_in,
                              void* d_out, int out_size) {
    const float* x    = (const float*)d_in[0];
    const float* mask = (const float*)d_in[1];
    const float* Wv   = (const float*)d_in[2];
    const float* bv   = (const float*)d_in[3];
    const float* Wk   = (const float*)d_in[4];
    const float* bk   = (const float*)d_in[5];
    const float* Wq   = (const float*)d_in[6];
    const float* bq   = (const float*)d_in[7];
    float* out = (float*)d_out;

    cudaFuncSetAttribute(proj_kernel, cudaFuncAttributeMaxDynamicSharedMemorySize,
                         49152);
    cudaFuncSetAttribute(attn_mma, cudaFuncAttributeMaxDynamicSharedMemorySize,
                         SMEM_ATT);

    proj_kernel<<<dim3(1024, 3, 1), 256, 49152>>>(x, Wq, bq, Wk, bk, Wv, bv);
    attn_mma<<<512, 256, SMEM_ATT>>>(mask, out);
}

// round 9
// speedup vs baseline: 1.6387x; 1.2784x over previous
#include <cuda_runtime.h>
#include <cstdint>
#include <cstddef>

#define BB 32
#define NN 2048
#define DD 128
#define HH 128

// Scratch for q/k/v activations (allocation-free rule: static device arrays).
__device__ float g_q[BB * NN * HH];
__device__ float g_k[BB * NN * HH];
__device__ float g_v[BB * NN * HH];

// ---------- packed f32x2 helpers (projection kernel) ----------
__device__ __forceinline__ unsigned long long pk2(float lo, float hi) {
    unsigned long long r;
    asm("mov.b64 %0, {%1, %2};" : "=l"(r) : "f"(lo), "f"(hi));
    return r;
}
__device__ __forceinline__ float2 upk2(unsigned long long p) {
    float2 f;
    asm("mov.b64 {%0, %1}, %2;" : "=f"(f.x), "=f"(f.y) : "l"(p));
    return f;
}
__device__ __forceinline__ unsigned long long f2fma(unsigned long long a,
                                                    unsigned long long b,
                                                    unsigned long long c) {
    unsigned long long d;
    asm("fma.rn.f32x2 %0, %1, %2, %3;" : "=l"(d) : "l"(a), "l"(b), "l"(c));
    return d;
}

__device__ __forceinline__ uint32_t tf32r(float x) {
    uint32_t r;
    asm("cvt.rna.tf32.f32 %0, %1;" : "=r"(r) : "f"(x));
    return r;
}

// warp mma: D(16x8) += A(16x8,row,tf32) * B(8x8,col,tf32), fp32 accum
__device__ __forceinline__ void mma16n8k8(float* c, const uint32_t* a,
                                          uint32_t b0, uint32_t b1) {
    asm volatile(
        "mma.sync.aligned.m16n8k8.row.col.f32.tf32.tf32.f32 "
        "{%0,%1,%2,%3}, {%4,%5,%6,%7}, {%8,%9}, {%0,%1,%2,%3};"
        : "+f"(c[0]), "+f"(c[1]), "+f"(c[2]), "+f"(c[3])
        : "r"(a[0]), "r"(a[1]), "r"(a[2]), "r"(a[3]), "r"(b0), "r"(b1));
}

__device__ __forceinline__ uint32_t smem_u32(const void* p) {
    uint32_t a;
    asm("{ .reg .u64 t; cvta.to.shared.u64 t, %1; cvt.u32.u64 %0, t; }"
        : "=r"(a) : "l"(p));
    return a;
}

#define CP_ASYNC16(dst, src)                                                \
    asm volatile("cp.async.cg.shared.global [%0], [%1], 16;" ::             \
                     "r"(dst), "l"(src) : "memory")
#define CP_COMMIT() asm volatile("cp.async.commit_group;" ::: "memory")
#define CP_WAIT0() asm volatile("cp.async.wait_group 0;" ::: "memory")

// ============================================================
// Kernel A: fused QKV projection, out = tanh(x @ W + b)  (FFMA2)
// Stores tf32-PRE-ROUNDED values. For q and k, the feature (h) dim is
// permuted within 8-groups: cc -> (cc&3)*2 + (cc>>2)  (QK^T invariant;
// lets the attention kernel fetch mma fragments with 8-byte loads).
// ============================================================
__global__ __launch_bounds__(256, 1) void proj_kernel(
    const float* __restrict__ x,
    const float* __restrict__ Wq, const float* __restrict__ bq,
    const float* __restrict__ Wk, const float* __restrict__ bk,
    const float* __restrict__ Wv, const float* __restrict__ bv) {
    extern __shared__ float sm[];
    float* xs = sm;              // 64*128
    float* ws = sm + 64 * 128;   // 32*128

    const float* W;
    const float* bias;
    float* outp;
    bool permute;
    if (blockIdx.y == 0)      { W = Wq; bias = bq; outp = g_q; permute = true; }
    else if (blockIdx.y == 1) { W = Wk; bias = bk; outp = g_k; permute = true; }
    else                      { W = Wv; bias = bv; outp = g_v; permute = false; }

    const int tid = threadIdx.x;
    const int rowg = tid >> 4;
    const int colg = tid & 15;
    const int row0 = blockIdx.x * 64;

    {
        const float4* src = reinterpret_cast<const float4*>(x + (size_t)row0 * DD);
        float4* dst = reinterpret_cast<float4*>(xs);
#pragma unroll
        for (int t = 0; t < 8; t++) dst[tid + t * 256] = src[tid + t * 256];
    }

    unsigned long long acc[4][4];
#pragma unroll
    for (int r = 0; r < 4; r++)
#pragma unroll
        for (int c = 0; c < 4; c++) acc[r][c] = 0ull;

#pragma unroll 1
    for (int chunk = 0; chunk < 4; chunk++) {
        const int kk0 = chunk * 32;
        __syncthreads();
        {
            const float4* src = reinterpret_cast<const float4*>(W + (size_t)kk0 * HH);
            float4* dst = reinterpret_cast<float4*>(ws);
#pragma unroll
            for (int t = 0; t < 4; t++) dst[tid + t * 256] = src[tid + t * 256];
        }
        __syncthreads();

#pragma unroll 2
        for (int kkl = 0; kkl < 32; kkl++) {
            const int kk = kk0 + kkl;
            float xv[4];
#pragma unroll
            for (int r = 0; r < 4; r++) xv[r] = xs[(rowg * 4 + r) * DD + kk];
            float4 wa = *reinterpret_cast<const float4*>(ws + kkl * HH + colg * 4);
            float4 wb = *reinterpret_cast<const float4*>(ws + kkl * HH + 64 + colg * 4);
            unsigned long long wp[4];
            wp[0] = *reinterpret_cast<unsigned long long*>(&wa.x);
            wp[1] = *reinterpret_cast<unsigned long long*>(&wa.z);
            wp[2] = *reinterpret_cast<unsigned long long*>(&wb.x);
            wp[3] = *reinterpret_cast<unsigned long long*>(&wb.z);
#pragma unroll
            for (int r = 0; r < 4; r++) {
                unsigned long long xp = pk2(xv[r], xv[r]);
#pragma unroll
                for (int c = 0; c < 4; c++) acc[r][c] = f2fma(xp, wp[c], acc[r][c]);
            }
        }
    }

    float4 ba = *reinterpret_cast<const float4*>(bias + colg * 4);
    float4 bb = *reinterpret_cast<const float4*>(bias + 64 + colg * 4);
    const bool oddc = (colg & 1);
    const int gbase = (colg >> 1) * 8 + (oddc ? 4 : 0);
#pragma unroll
    for (int r = 0; r < 4; r++) {
        float2 a0 = upk2(acc[r][0]);
        float2 a1 = upk2(acc[r][1]);
        float2 a2 = upk2(acc[r][2]);
        float2 a3 = upk2(acc[r][3]);
        float v[8];
        v[0] = __uint_as_float(tf32r(tanhf(a0.x + ba.x)));
        v[1] = __uint_as_float(tf32r(tanhf(a0.y + ba.y)));
        v[2] = __uint_as_float(tf32r(tanhf(a1.x + ba.z)));
        v[3] = __uint_as_float(tf32r(tanhf(a1.y + ba.w)));
        v[4] = __uint_as_float(tf32r(tanhf(a2.x + bb.x)));
        v[5] = __uint_as_float(tf32r(tanhf(a2.y + bb.y)));
        v[6] = __uint_as_float(tf32r(tanhf(a3.x + bb.z)));
        v[7] = __uint_as_float(tf32r(tanhf(a3.y + bb.w)));
        float* orow = outp + (size_t)(row0 + rowg * 4 + r) * HH;
        if (permute) {
            float p[8];
#pragma unroll
            for (int i = 0; i < 8; i++)
                p[i] = __shfl_xor_sync(0xffffffffu, v[i], 1);
            float4 lo, hi;
            if (!oddc) {
                lo.x = v[0]; lo.y = p[0]; lo.z = v[1]; lo.w = p[1];
                hi.x = v[4]; hi.y = p[4]; hi.z = v[5]; hi.w = p[5];
            } else {
                lo.x = p[2]; lo.y = v[2]; lo.z = p[3]; lo.w = v[3];
                hi.x = p[6]; hi.y = v[6]; hi.z = p[7]; hi.w = v[7];
            }
            *reinterpret_cast<float4*>(orow + gbase) = lo;
            *reinterpret_cast<float4*>(orow + 64 + gbase) = hi;
        } else {
            float4 oa, ob;
            oa.x = v[0]; oa.y = v[1]; oa.z = v[2]; oa.w = v[3];
            ob.x = v[4]; ob.y = v[5]; ob.z = v[6]; ob.w = v[7];
            *reinterpret_cast<float4*>(orow + colg * 4) = oa;
            *reinterpret_cast<float4*>(orow + 64 + colg * 4) = ob;
        }
    }
}

// ============================================================
// Kernel B: tf32 mma.sync flash attention v7 — OCCUPANCY build.
//  - __launch_bounds__(256, 2): regs <=128, 2 CTAs/SM -> 4 warps/SMSP
//  - Q in smem (staged once); no persistent qa registers
//  - j-stage 32, single K/V buffer (copy exposure covered by co-resident CTA)
//  - LDW 136 everywhere: conflict-free LDS.64 fragment fetches (8*qp+2*ql)
//  - per-stage: mask prefetch -> QK (k-outer, sf[4]) -> per-nb convert+PV
// smem (words): Q[128][136] | K[32][136] | V[32][136]  = 104448 bytes
// ============================================================
#define LDW 136
#define KS_OFF (128 * LDW)
#define VS_OFF (KS_OFF + 32 * LDW)
#define SMEM_ATT ((VS_OFF + 32 * LDW) * 4)

__global__ __launch_bounds__(256, 2) void attn_mma(
    const float* __restrict__ mask, float* __restrict__ out) {
    extern __shared__ uint32_t smw[];
    uint32_t* Qs = smw;
    uint32_t* Ks = smw + KS_OFF;
    uint32_t* Vs = smw + VS_OFF;
    const uint32_t smb = smem_u32(smw);

    const int tid = threadIdx.x;
    const int lane = tid & 31;
    const int w = tid >> 5;
    const int b = blockIdx.x >> 4;
    const int i0 = (blockIdx.x & 15) << 7;
    const int qp = lane >> 2;
    const int ql = lane & 3;
    const int r0 = w * 16 + qp;

    const float* qg = g_q + ((size_t)(b * NN) + i0) * HH;
    const float* kg = g_k + (size_t)(b * NN) * HH;
    const float* vg = g_v + (size_t)(b * NN) * HH;

    // ---- prologue: stage Q (once) + K0/V0 ----
#pragma unroll
    for (int t = 0; t < 16; t++) {
        const int idx = tid + t * 256;       // 0..4095
        const int row = idx >> 5, c4 = idx & 31;
        CP_ASYNC16(smb + (uint32_t)(row * LDW + c4 * 4) * 4, qg + idx * 4);
    }
#pragma unroll
    for (int t = 0; t < 4; t++) {
        const int idx = tid + t * 256;       // 0..1023
        const int row = idx >> 5, c4 = idx & 31;
        CP_ASYNC16(smb + (uint32_t)(KS_OFF + row * LDW + c4 * 4) * 4,
                   kg + idx * 4);
        CP_ASYNC16(smb + (uint32_t)(VS_OFF + row * LDW + c4 * 4) * 4,
                   vg + idx * 4);
    }
    CP_COMMIT();

    float oa[16][4];
#pragma unroll
    for (int h = 0; h < 16; h++)
#pragma unroll
        for (int c = 0; c < 4; c++) oa[h][c] = 0.0f;
    float ls0 = 0.0f, ls1 = 0.0f;

    const float* mrow0 = mask + ((size_t)(b * NN) + i0 + r0) * NN + 2 * ql;
    const float* mrow1 = mrow0 + (size_t)8 * NN;

    const int L0 = qp * 4 + (ql >> 1);
    const bool odd = (ql & 1);

    const uint32_t* qbase = Qs + r0 * LDW + 2 * ql;

#pragma unroll 1
    for (int jt = 0; jt < 64; jt++) {
        const int j0 = jt << 5;
        CP_WAIT0();
        __syncthreads();   // K[jt], V[jt] (and Q on jt=0) visible

        // ---- prefetch this stage's mask (hidden behind QK) ----
        float2 mh0[4], mh1[4];
#pragma unroll
        for (int nb = 0; nb < 4; nb++) {
            const int jcol = j0 + nb * 8;
            mh0[nb] = __ldg(reinterpret_cast<const float2*>(mrow0 + jcol));
            mh1[nb] = __ldg(reinterpret_cast<const float2*>(mrow1 + jcol));
        }

        // ---- S = Q K^T : k-outer, q-fragment shared across 4 nb ----
        float sf[4][4];
#pragma unroll
        for (int nb = 0; nb < 4; nb++)
#pragma unroll
            for (int c = 0; c < 4; c++) sf[nb][c] = 0.0f;

#pragma unroll
        for (int k = 0; k < 16; k++) {
            uint2 q0 = *reinterpret_cast<const uint2*>(qbase + k * 8);
            uint2 q1 = *reinterpret_cast<const uint2*>(qbase + k * 8 + 8 * LDW);
            uint32_t qa[4] = {q0.x, q1.x, q0.y, q1.y};
#pragma unroll
            for (int nb = 0; nb < 4; nb++) {
                uint2 kb = *reinterpret_cast<const uint2*>(
                    Ks + (nb * 8 + qp) * LDW + k * 8 + 2 * ql);
                mma16n8k8(sf[nb], qa, kb.x, kb.y);
            }
        }

        // ---- per-nb: mask + exp + D->A conversion + PV ----
#pragma unroll
        for (int nb = 0; nb < 4; nb++) {
            uint32_t u0 = (mh0[nb].x != 0.0f) ? tf32r(__expf(sf[nb][0] - 40.0f)) : 0u;
            uint32_t u1 = (mh0[nb].y != 0.0f) ? tf32r(__expf(sf[nb][1] - 40.0f)) : 0u;
            uint32_t u2 = (mh1[nb].x != 0.0f) ? tf32r(__expf(sf[nb][2] - 40.0f)) : 0u;
            uint32_t u3 = (mh1[nb].y != 0.0f) ? tf32r(__expf(sf[nb][3] - 40.0f)) : 0u;
            ls0 += __uint_as_float(u0) + __uint_as_float(u1);
            ls1 += __uint_as_float(u2) + __uint_as_float(u3);
            uint32_t pa[4];
            {
                uint32_t t00 = __shfl_sync(0xffffffffu, u0, L0);
                uint32_t t01 = __shfl_sync(0xffffffffu, u1, L0);
                uint32_t t10 = __shfl_sync(0xffffffffu, u2, L0);
                uint32_t t11 = __shfl_sync(0xffffffffu, u3, L0);
                uint32_t t20 = __shfl_sync(0xffffffffu, u0, L0 + 2);
                uint32_t t21 = __shfl_sync(0xffffffffu, u1, L0 + 2);
                uint32_t t30 = __shfl_sync(0xffffffffu, u2, L0 + 2);
                uint32_t t31 = __shfl_sync(0xffffffffu, u3, L0 + 2);
                pa[0] = odd ? t01 : t00;
                pa[1] = odd ? t11 : t10;
                pa[2] = odd ? t21 : t20;
                pa[3] = odd ? t31 : t30;
            }
            const uint32_t* vb = Vs + (nb * 8 + ql) * LDW + qp;
#pragma unroll
            for (int h = 0; h < 16; h++) {
                mma16n8k8(oa[h], pa, vb[h * 8], vb[h * 8 + 4 * LDW]);
            }
        }

        __syncthreads();   // all warps done with K/V stage jt
        if (jt < 63) {
            const float* kn = kg + ((size_t)(j0 + 32)) * HH;
            const float* vn = vg + ((size_t)(j0 + 32)) * HH;
#pragma unroll
            for (int t = 0; t < 4; t++) {
                const int idx = tid + t * 256;
                const int row = idx >> 5, c4 = idx & 31;
                CP_ASYNC16(smb + (uint32_t)(KS_OFF + row * LDW + c4 * 4) * 4,
                           kn + idx * 4);
                CP_ASYNC16(smb + (uint32_t)(VS_OFF + row * LDW + c4 * 4) * 4,
                           vn + idx * 4);
            }
            CP_COMMIT();
        }
    }

    // ---- epilogue: quad reduction, normalize, store ----
    ls0 += __shfl_xor_sync(0xffffffffu, ls0, 1);
    ls0 += __shfl_xor_sync(0xffffffffu, ls0, 2);
    ls1 += __shfl_xor_sync(0xffffffffu, ls1, 1);
    ls1 += __shfl_xor_sync(0xffffffffu, ls1, 2);
    const float inv0 = 1.0f / ls0;
    const float inv1 = 1.0f / ls1;
    float* orow0 = out + ((size_t)(b * NN) + i0 + r0) * HH + 2 * ql;
    float* orow1 = orow0 + (size_t)8 * HH;
#pragma unroll
    for (int h = 0; h < 16; h++) {
        float2 v0, v1;
        v0.x = oa[h][0] * inv0; v0.y = oa[h][1] * inv0;
        v1.x = oa[h][2] * inv1; v1.y = oa[h][3] * inv1;
        *reinterpret_cast<float2*>(orow0 + h * 8) = v0;
        *reinterpret_cast<float2*>(orow1 + h * 8) = v1;
    }
}

extern "C" void kernel_launch(void* const* d_in, const int* in_sizes, int n_in,
                              void* d_out, int out_size) {
    const float* x    = (const float*)d_in[0];
    const float* mask = (const float*)d_in[1];
    const float* Wv   = (const float*)d_in[2];
    const float* bv   = (const float*)d_in[3];
    const float* Wk   = (const float*)d_in[4];
    const float* bk   = (const float*)d_in[5];
    const float* Wq   = (const float*)d_in[6];
    const float* bq   = (const float*)d_in[7];
    float* out = (float*)d_out;

    cudaFuncSetAttribute(proj_kernel, cudaFuncAttributeMaxDynamicSharedMemorySize,
                         49152);
    cudaFuncSetAttribute(attn_mma, cudaFuncAttributeMaxDynamicSharedMemorySize,
                         SMEM_ATT);

    proj_kernel<<<dim3(1024, 3, 1), 256, 49152>>>(x, Wq, bq, Wk, bk, Wv, bv);
    attn_mma<<<512, 256, SMEM_ATT>>>(mask, out);
}

// round 10
// speedup vs baseline: 2.1947x; 1.3393x over previous
#include <cuda_runtime.h>
#include <cstdint>
#include <cstddef>

#define BB 32
#define NN 2048
#define DD 128
#define HH 128

// Scratch for q/k/v activations (allocation-free rule: static device arrays).
// g_v is reused as fp16x2 j-pair-packed storage (uint32 words [B*1024][128]).
__device__ float g_q[BB * NN * HH];
__device__ float g_k[BB * NN * HH];
__device__ float g_v[BB * NN * HH];

// ---------- packed f32x2 helpers (projection kernel) ----------
__device__ __forceinline__ unsigned long long pk2(float lo, float hi) {
    unsigned long long r;
    asm("mov.b64 %0, {%1, %2};" : "=l"(r) : "f"(lo), "f"(hi));
    return r;
}
__device__ __forceinline__ float2 upk2(unsigned long long p) {
    float2 f;
    asm("mov.b64 {%0, %1}, %2;" : "=f"(f.x), "=f"(f.y) : "l"(p));
    return f;
}
__device__ __forceinline__ unsigned long long f2fma(unsigned long long a,
                                                    unsigned long long b,
                                                    unsigned long long c) {
    unsigned long long d;
    asm("fma.rn.f32x2 %0, %1, %2, %3;" : "=l"(d) : "l"(a), "l"(b), "l"(c));
    return d;
}

__device__ __forceinline__ uint32_t tf32r(float x) {
    uint32_t r;
    asm("cvt.rna.tf32.f32 %0, %1;" : "=r"(r) : "f"(x));
    return r;
}
// pack two fp32 -> fp16x2 (lo = a, hi = b), saturating to finite
__device__ __forceinline__ uint32_t h2pack(float a, float b) {
    uint32_t r;
    asm("cvt.rn.satfinite.f16x2.f32 %0, %1, %2;" : "=r"(r) : "f"(b), "f"(a));
    return r;
}

// warp mma: D(16x8) += A(16x8,row,tf32) * B(8x8,col,tf32), fp32 accum
__device__ __forceinline__ void mma16n8k8(float* c, const uint32_t* a,
                                          uint32_t b0, uint32_t b1) {
    asm volatile(
        "mma.sync.aligned.m16n8k8.row.col.f32.tf32.tf32.f32 "
        "{%0,%1,%2,%3}, {%4,%5,%6,%7}, {%8,%9}, {%0,%1,%2,%3};"
        : "+f"(c[0]), "+f"(c[1]), "+f"(c[2]), "+f"(c[3])
        : "r"(a[0]), "r"(a[1]), "r"(a[2]), "r"(a[3]), "r"(b0), "r"(b1));
}
// warp mma: D(16x8) += A(16x16,row,f16) * B(16x8,col,f16), fp32 accum
__device__ __forceinline__ void mma16n8k16h(float* c, const uint32_t* a,
                                            uint32_t b0, uint32_t b1) {
    asm volatile(
        "mma.sync.aligned.m16n8k16.row.col.f32.f16.f16.f32 "
        "{%0,%1,%2,%3}, {%4,%5,%6,%7}, {%8,%9}, {%0,%1,%2,%3};"
        : "+f"(c[0]), "+f"(c[1]), "+f"(c[2]), "+f"(c[3])
        : "r"(a[0]), "r"(a[1]), "r"(a[2]), "r"(a[3]), "r"(b0), "r"(b1));
}

__device__ __forceinline__ uint32_t smem_u32(const void* p) {
    uint32_t a;
    asm("{ .reg .u64 t; cvta.to.shared.u64 t, %1; cvt.u32.u64 %0, t; }"
        : "=r"(a) : "l"(p));
    return a;
}

#define CP_ASYNC16(dst, src)                                                \
    asm volatile("cp.async.cg.shared.global [%0], [%1], 16;" ::             \
                     "r"(dst), "l"(src) : "memory")
#define CP_COMMIT() asm volatile("cp.async.commit_group;" ::: "memory")
#define CP_WAIT0() asm volatile("cp.async.wait_group 0;" ::: "memory")

// ============================================================
// Kernel A: fused QKV projection, out = tanh(x @ W + b)  (FFMA2)
// q,k: tf32-pre-rounded, h-dim permuted within 8-groups (cc -> (cc&3)*2+(cc>>2)).
// v: fp16x2 j-pair-packed: word[jp][h] = (v[2jp][h], v[2jp+1][h]), h natural.
// ============================================================
__global__ __launch_bounds__(256, 1) void proj_kernel(
    const float* __restrict__ x,
    const float* __restrict__ Wq, const float* __restrict__ bq,
    const float* __restrict__ Wk, const float* __restrict__ bk,
    const float* __restrict__ Wv, const float* __restrict__ bv) {
    extern __shared__ float sm[];
    float* xs = sm;              // 64*128
    float* ws = sm + 64 * 128;   // 32*128

    const float* W;
    const float* bias;
    bool isV;
    float* outp;
    if (blockIdx.y == 0)      { W = Wq; bias = bq; outp = g_q; isV = false; }
    else if (blockIdx.y == 1) { W = Wk; bias = bk; outp = g_k; isV = false; }
    else                      { W = Wv; bias = bv; outp = g_v; isV = true; }

    const int tid = threadIdx.x;
    const int rowg = tid >> 4;
    const int colg = tid & 15;
    const int row0 = blockIdx.x * 64;

    {
        const float4* src = reinterpret_cast<const float4*>(x + (size_t)row0 * DD);
        float4* dst = reinterpret_cast<float4*>(xs);
#pragma unroll
        for (int t = 0; t < 8; t++) dst[tid + t * 256] = src[tid + t * 256];
    }

    unsigned long long acc[4][4];
#pragma unroll
    for (int r = 0; r < 4; r++)
#pragma unroll
        for (int c = 0; c < 4; c++) acc[r][c] = 0ull;

#pragma unroll 1
    for (int chunk = 0; chunk < 4; chunk++) {
        const int kk0 = chunk * 32;
        __syncthreads();
        {
            const float4* src = reinterpret_cast<const float4*>(W + (size_t)kk0 * HH);
            float4* dst = reinterpret_cast<float4*>(ws);
#pragma unroll
            for (int t = 0; t < 4; t++) dst[tid + t * 256] = src[tid + t * 256];
        }
        __syncthreads();

#pragma unroll 2
        for (int kkl = 0; kkl < 32; kkl++) {
            const int kk = kk0 + kkl;
            float xv[4];
#pragma unroll
            for (int r = 0; r < 4; r++) xv[r] = xs[(rowg * 4 + r) * DD + kk];
            float4 wa = *reinterpret_cast<const float4*>(ws + kkl * HH + colg * 4);
            float4 wb = *reinterpret_cast<const float4*>(ws + kkl * HH + 64 + colg * 4);
            unsigned long long wp[4];
            wp[0] = *reinterpret_cast<unsigned long long*>(&wa.x);
            wp[1] = *reinterpret_cast<unsigned long long*>(&wa.z);
            wp[2] = *reinterpret_cast<unsigned long long*>(&wb.x);
            wp[3] = *reinterpret_cast<unsigned long long*>(&wb.z);
#pragma unroll
            for (int r = 0; r < 4; r++) {
                unsigned long long xp = pk2(xv[r], xv[r]);
#pragma unroll
                for (int c = 0; c < 4; c++) acc[r][c] = f2fma(xp, wp[c], acc[r][c]);
            }
        }
    }

    float4 ba = *reinterpret_cast<const float4*>(bias + colg * 4);
    float4 bb = *reinterpret_cast<const float4*>(bias + 64 + colg * 4);

    float vall[4][8];
#pragma unroll
    for (int r = 0; r < 4; r++) {
        float2 a0 = upk2(acc[r][0]);
        float2 a1 = upk2(acc[r][1]);
        float2 a2 = upk2(acc[r][2]);
        float2 a3 = upk2(acc[r][3]);
        vall[r][0] = tanhf(a0.x + ba.x);
        vall[r][1] = tanhf(a0.y + ba.y);
        vall[r][2] = tanhf(a1.x + ba.z);
        vall[r][3] = tanhf(a1.y + ba.w);
        vall[r][4] = tanhf(a2.x + bb.x);
        vall[r][5] = tanhf(a2.y + bb.y);
        vall[r][6] = tanhf(a3.x + bb.z);
        vall[r][7] = tanhf(a3.y + bb.w);
    }

    if (!isV) {
        // q,k: tf32 round + h-permute, repacked to float4 via shfl pair swap
        const bool oddc = (colg & 1);
        const int gbase = (colg >> 1) * 8 + (oddc ? 4 : 0);
#pragma unroll
        for (int r = 0; r < 4; r++) {
            float v[8];
#pragma unroll
            for (int i = 0; i < 8; i++)
                v[i] = __uint_as_float(tf32r(vall[r][i]));
            float p[8];
#pragma unroll
            for (int i = 0; i < 8; i++)
                p[i] = __shfl_xor_sync(0xffffffffu, v[i], 1);
            float4 lo, hi;
            if (!oddc) {
                lo.x = v[0]; lo.y = p[0]; lo.z = v[1]; lo.w = p[1];
                hi.x = v[4]; hi.y = p[4]; hi.z = v[5]; hi.w = p[5];
            } else {
                lo.x = p[2]; lo.y = v[2]; lo.z = p[3]; lo.w = v[3];
                hi.x = p[6]; hi.y = v[6]; hi.z = p[7]; hi.w = v[7];
            }
            float* orow = outp + (size_t)(row0 + rowg * 4 + r) * HH;
            *reinterpret_cast<float4*>(orow + gbase) = lo;
            *reinterpret_cast<float4*>(orow + 64 + gbase) = hi;
        }
    } else {
        // v: fp16x2 j-pair pack; word[jp][h] = (row 2jp, row 2jp+1)
        uint32_t* v2 = reinterpret_cast<uint32_t*>(g_v);
#pragma unroll
        for (int rp = 0; rp < 2; rp++) {
            const size_t jp = (size_t)(row0 + rowg * 4) / 2 + rp;
            uint32_t wv[8];
#pragma unroll
            for (int i = 0; i < 8; i++)
                wv[i] = h2pack(vall[2 * rp][i], vall[2 * rp + 1][i]);
            uint4 lo, hi;
            lo.x = wv[0]; lo.y = wv[1]; lo.z = wv[2]; lo.w = wv[3];
            hi.x = wv[4]; hi.y = wv[5]; hi.z = wv[6]; hi.w = wv[7];
            uint32_t* orow = v2 + jp * HH;
            *reinterpret_cast<uint4*>(orow + colg * 4) = lo;
            *reinterpret_cast<uint4*>(orow + 64 + colg * 4) = hi;
        }
    }
}

// ============================================================
// Kernel B: flash attention v8 — tf32 QK + fp16 PV.
//  - __launch_bounds__(256, 2); Q in smem; j-stage 32
//  - PV: m16n8k16 f16 (half the MMAs), V fp16x2 j-pair layout (half LDS bytes)
//  - P D-frag -> A-frag by cvt-pack only (ZERO shfls); offset exp(s-10)
//  - V double-buffered (copy at stage top, hidden); K copy after QK sync
// smem (words): Q[128][136] | K[32][136] | Vt 2x[16][136]  = 104448 bytes
// ============================================================
#define LDW 136
#define KS_OFF (128 * LDW)
#define VT_OFF (KS_OFF + 32 * LDW)
#define VT_STRIDE (16 * LDW)
#define SMEM_ATT ((VT_OFF + 2 * VT_STRIDE) * 4)

__global__ __launch_bounds__(256, 2) void attn_mma(
    const float* __restrict__ mask, float* __restrict__ out) {
    extern __shared__ uint32_t smw[];
    uint32_t* Qs = smw;
    uint32_t* Ks = smw + KS_OFF;
    const uint32_t smb = smem_u32(smw);

    const int tid = threadIdx.x;
    const int lane = tid & 31;
    const int w = tid >> 5;
    const int b = blockIdx.x >> 4;
    const int i0 = (blockIdx.x & 15) << 7;
    const int qp = lane >> 2;
    const int ql = lane & 3;
    const int r0 = w * 16 + qp;

    const float* qg = g_q + ((size_t)(b * NN) + i0) * HH;
    const float* kg = g_k + (size_t)(b * NN) * HH;
    const uint32_t* vg2 =
        reinterpret_cast<const uint32_t*>(g_v) + (size_t)b * 1024 * HH;

    // ---- prologue: stage Q + K0 + V0(buf0) ----
#pragma unroll
    for (int t = 0; t < 16; t++) {
        const int idx = tid + t * 256;       // 0..4095
        const int row = idx >> 5, c4 = idx & 31;
        CP_ASYNC16(smb + (uint32_t)(row * LDW + c4 * 4) * 4, qg + idx * 4);
    }
#pragma unroll
    for (int t = 0; t < 4; t++) {
        const int idx = tid + t * 256;       // 0..1023
        const int row = idx >> 5, c4 = idx & 31;
        CP_ASYNC16(smb + (uint32_t)(KS_OFF + row * LDW + c4 * 4) * 4,
                   kg + idx * 4);
    }
#pragma unroll
    for (int t = 0; t < 2; t++) {
        const int idx = tid + t * 256;       // 0..511
        const int row = idx >> 5, c4 = idx & 31;
        CP_ASYNC16(smb + (uint32_t)(VT_OFF + row * LDW + c4 * 4) * 4,
                   vg2 + (size_t)row * HH + c4 * 4);
    }
    CP_COMMIT();

    float oa[16][4];
#pragma unroll
    for (int h = 0; h < 16; h++)
#pragma unroll
        for (int c = 0; c < 4; c++) oa[h][c] = 0.0f;
    float ls0 = 0.0f, ls1 = 0.0f;

    const float* mrow0 = mask + ((size_t)(b * NN) + i0 + r0) * NN + 2 * ql;
    const float* mrow1 = mrow0 + (size_t)8 * NN;

    const uint32_t* qbase = Qs + r0 * LDW + 2 * ql;

#pragma unroll 1
    for (int jt = 0; jt < 64; jt++) {
        const int j0 = jt << 5;
        CP_WAIT0();
        __syncthreads();   // stage jt (K + V buf jt&1) visible; prior stage done

        // ---- issue V copy for jt+1 into other buffer (fully hidden) ----
        if (jt < 63) {
            const uint32_t vdst = smb +
                (uint32_t)(VT_OFF + ((jt + 1) & 1) * VT_STRIDE) * 4;
            const uint32_t* vn = vg2 + (size_t)((jt + 1) * 16) * HH;
#pragma unroll
            for (int t = 0; t < 2; t++) {
                const int idx = tid + t * 256;
                const int row = idx >> 5, c4 = idx & 31;
                CP_ASYNC16(vdst + (uint32_t)(row * LDW + c4 * 4) * 4,
                           vn + (size_t)row * HH + c4 * 4);
            }
            CP_COMMIT();
        }

        // ---- prefetch this stage's mask (hidden behind QK) ----
        float2 mh0[4], mh1[4];
#pragma unroll
        for (int nb = 0; nb < 4; nb++) {
            const int jcol = j0 + nb * 8;
            mh0[nb] = __ldg(reinterpret_cast<const float2*>(mrow0 + jcol));
            mh1[nb] = __ldg(reinterpret_cast<const float2*>(mrow1 + jcol));
        }

        // ---- S = Q K^T : k-outer, tf32 ----
        float sf[4][4];
#pragma unroll
        for (int nb = 0; nb < 4; nb++)
#pragma unroll
            for (int c = 0; c < 4; c++) sf[nb][c] = 0.0f;

#pragma unroll
        for (int k = 0; k < 16; k++) {
            uint2 q0 = *reinterpret_cast<const uint2*>(qbase + k * 8);
            uint2 q1 = *reinterpret_cast<const uint2*>(qbase + k * 8 + 8 * LDW);
            uint32_t qa[4] = {q0.x, q1.x, q0.y, q1.y};
#pragma unroll
            for (int nb = 0; nb < 4; nb++) {
                uint2 kb = *reinterpret_cast<const uint2*>(
                    Ks + (nb * 8 + qp) * LDW + k * 8 + 2 * ql);
                mma16n8k8(sf[nb], qa, kb.x, kb.y);
            }
        }

        __syncthreads();   // all warps done reading Ks
        if (jt < 63) {
            const float* kn = kg + ((size_t)(j0 + 32)) * HH;
#pragma unroll
            for (int t = 0; t < 4; t++) {
                const int idx = tid + t * 256;
                const int row = idx >> 5, c4 = idx & 31;
                CP_ASYNC16(smb + (uint32_t)(KS_OFF + row * LDW + c4 * 4) * 4,
                           kn + idx * 4);
            }
            CP_COMMIT();
        }

        // ---- per nb-pair: mask + exp(s-10) + fp16 pack + PV (m16n8k16) ----
        const uint32_t* sVt = smw + VT_OFF + (jt & 1) * VT_STRIDE;
#pragma unroll
        for (int m = 0; m < 2; m++) {
            const int nE = 2 * m, nO = 2 * m + 1;
            float pE0 = (mh0[nE].x != 0.0f) ? __expf(sf[nE][0] - 10.0f) : 0.0f;
            float pE1 = (mh0[nE].y != 0.0f) ? __expf(sf[nE][1] - 10.0f) : 0.0f;
            float pE2 = (mh1[nE].x != 0.0f) ? __expf(sf[nE][2] - 10.0f) : 0.0f;
            float pE3 = (mh1[nE].y != 0.0f) ? __expf(sf[nE][3] - 10.0f) : 0.0f;
            float pO0 = (mh0[nO].x != 0.0f) ? __expf(sf[nO][0] - 10.0f) : 0.0f;
            float pO1 = (mh0[nO].y != 0.0f) ? __expf(sf[nO][1] - 10.0f) : 0.0f;
            float pO2 = (mh1[nO].x != 0.0f) ? __expf(sf[nO][2] - 10.0f) : 0.0f;
            float pO3 = (mh1[nO].y != 0.0f) ? __expf(sf[nO][3] - 10.0f) : 0.0f;
            ls0 += (pE0 + pE1) + (pO0 + pO1);
            ls1 += (pE2 + pE3) + (pO2 + pO3);
            uint32_t pa[4];
            pa[0] = h2pack(pE0, pE1);
            pa[1] = h2pack(pE2, pE3);
            pa[2] = h2pack(pO0, pO1);
            pa[3] = h2pack(pO2, pO3);

            const uint32_t* vb0 = sVt + (m * 8 + ql) * LDW + qp;
            const uint32_t* vb1 = sVt + (m * 8 + ql + 4) * LDW + qp;
#pragma unroll
            for (int h = 0; h < 16; h++) {
                mma16n8k16h(oa[h], pa, vb0[h * 8], vb1[h * 8]);
            }
        }
    }

    // ---- epilogue: quad reduction, normalize, store ----
    ls0 += __shfl_xor_sync(0xffffffffu, ls0, 1);
    ls0 += __shfl_xor_sync(0xffffffffu, ls0, 2);
    ls1 += __shfl_xor_sync(0xffffffffu, ls1, 1);
    ls1 += __shfl_xor_sync(0xffffffffu, ls1, 2);
    const float inv0 = 1.0f / ls0;
    const float inv1 = 1.0f / ls1;
    float* orow0 = out + ((size_t)(b * NN) + i0 + r0) * HH + 2 * ql;
    float* orow1 = orow0 + (size_t)8 * HH;
#pragma unroll
    for (int h = 0; h < 16; h++) {
        float2 v0, v1;
        v0.x = oa[h][0] * inv0; v0.y = oa[h][1] * inv0;
        v1.x = oa[h][2] * inv1; v1.y = oa[h][3] * inv1;
        *reinterpret_cast<float2*>(orow0 + h * 8) = v0;
        *reinterpret_cast<float2*>(orow1 + h * 8) = v1;
    }
}

extern "C" void kernel_launch(void* const* d_in, const int* in_sizes, int n_in,
                              void* d_out, int out_size) {
    const float* x    = (const float*)d_in[0];
    const float* mask = (const float*)d_in[1];
    const float* Wv   = (const float*)d_in[2];
    const float* bv   = (const float*)d_in[3];
    const float* Wk   = (const float*)d_in[4];
    const float* bk   = (const float*)d_in[5];
    const float* Wq   = (const float*)d_in[6];
    const float* bq   = (const float*)d_in[7];
    float* out = (float*)d_out;

    cudaFuncSetAttribute(proj_kernel, cudaFuncAttributeMaxDynamicSharedMemorySize,
                         49152);
    cudaFuncSetAttribute(attn_mma, cudaFuncAttributeMaxDynamicSharedMemorySize,
                         SMEM_ATT);

    proj_kernel<<<dim3(1024, 3, 1), 256, 49152>>>(x, Wq, bq, Wk, bk, Wv, bv);
    attn_mma<<<512, 256, SMEM_ATT>>>(mask, out);
}